// round 1
// baseline (speedup 1.0000x reference)
#include <cuda_runtime.h>

#define NRAYS_MAX 8192
#define S 128
#define H 64
#define GRIDR 64

// ---- packed f32x2 helpers (sm_100+ PTX; ptxas never auto-emits FFMA2) ----
__device__ __forceinline__ unsigned long long pack2(float v) {
    unsigned long long r;
    unsigned int u = __float_as_uint(v);
    asm("mov.b64 %0, {%1,%2};" : "=l"(r) : "r"(u), "r"(u));
    return r;
}
__device__ __forceinline__ void unpack2(unsigned long long v, float& lo, float& hi) {
    unsigned int a, b;
    asm("mov.b64 {%0,%1}, %2;" : "=r"(a), "=r"(b) : "l"(v));
    lo = __uint_as_float(a);
    hi = __uint_as_float(b);
}
__device__ __forceinline__ unsigned long long fma2(unsigned long long a,
                                                   unsigned long long b,
                                                   unsigned long long c) {
    unsigned long long d;
    asm("fma.rn.f32x2 %0, %1, %2, %3;" : "=l"(d) : "l"(a), "l"(b), "l"(c));
    return d;
}

__global__ void __launch_bounds__(128, 3) render_kernel(
    const float* __restrict__ rays_o, const float* __restrict__ rays_d,
    const float* __restrict__ near_, const float* __restrict__ far_,
    const float* __restrict__ jitter, const float* __restrict__ density,
    const float* __restrict__ W1, const float* __restrict__ b1,
    const float* __restrict__ W2, const float* __restrict__ b2,
    const float* __restrict__ Wsig, const float* __restrict__ bsig,
    const float* __restrict__ Wrgb, const float* __restrict__ brgb,
    float* __restrict__ out, int nrays)
{
    __shared__ __align__(16) float sW2[H * H];     // 16 KB
    __shared__ __align__(16) float sb2[H];
    __shared__ float sW1[3 * H];
    __shared__ float sb1[H];
    __shared__ float sWsig[H];
    __shared__ float sWrgb[H * 3];
    __shared__ float sbias4[4];                    // bsig, brgb[0..2]
    __shared__ float s_px[S], s_py[S], s_pz[S];
    __shared__ int   s_orig[S];
    __shared__ float s_alpha[S], s_r[S], s_g[S], s_b[S];
    __shared__ int   s_cnt;

    const int tid = threadIdx.x;

    // ---- load weights to shared once per block (persistent blocks) ----
    for (int i = tid; i < 3 * H; i += 128) sW1[i] = W1[i];
    for (int i = tid; i < H; i += 128) {
        sb1[i] = b1[i]; sb2[i] = b2[i]; sWsig[i] = Wsig[i];
    }
    for (int i = tid; i < H * H; i += 128) sW2[i] = W2[i];
    for (int i = tid; i < H * 3; i += 128) sWrgb[i] = Wrgb[i];
    if (tid == 0) {
        sbias4[0] = bsig[0]; sbias4[1] = brgb[0];
        sbias4[2] = brgb[1]; sbias4[3] = brgb[2];
    }
    __syncthreads();

    for (int ray = blockIdx.x; ray < nrays; ray += gridDim.x) {
        const float ox = rays_o[ray * 3 + 0], oy = rays_o[ray * 3 + 1], oz = rays_o[ray * 3 + 2];
        const float dx = rays_d[ray * 3 + 0], dy = rays_d[ray * 3 + 1], dz = rays_d[ray * 3 + 2];
        const float nr = near_[ray], fr = far_[ray];
        const float step = (fr - nr) * (1.0f / (float)S);

        if (tid == 0) s_cnt = 0;
        s_alpha[tid] = 0.0f; s_r[tid] = 0.0f; s_g[tid] = 0.0f; s_b[tid] = 0.0f;
        __syncthreads();

        // ---- phase A: grid occupancy test + compaction ----
        const float z = nr + (float)tid * step;
        const float px0 = ox + z * dx;
        const float py0 = oy + z * dy;
        const float pz0 = oz + z * dz;
        // AABB: min=(-1.25,-1.55,-1.25), extent = 2.5 in all dims
        const float fx = ((px0 + 1.25f) * 0.4f) * 64.0f;
        const float fy = ((py0 + 1.55f) * 0.4f) * 64.0f;
        const float fz = ((pz0 + 1.25f) * 0.4f) * 64.0f;
        const int ix = (int)floorf(fx);
        const int iy = (int)floorf(fy);
        const int iz = (int)floorf(fz);
        const bool inb = (ix >= 0) & (ix < GRIDR) & (iy >= 0) & (iy < GRIDR) &
                         (iz >= 0) & (iz < GRIDR);
        bool active = false;
        if (inb) active = __ldg(&density[(ix * GRIDR + iy) * GRIDR + iz]) > 0.5f;

        float zv = active ? z : 0.0f;
        zv += jitter[ray * S + tid] * step;

        if (active) {
            const int slot = atomicAdd(&s_cnt, 1);
            s_px[slot] = ox + zv * dx;
            s_py[slot] = oy + zv * dy;
            s_pz[slot] = oz + zv * dz;
            s_orig[slot] = tid;
        }
        __syncthreads();

        // ---- phase B: MLP on compacted active samples ----
        const int nact = s_cnt;
        if (tid < nact) {
            const float px = s_px[tid], py = s_py[tid], pz = s_pz[tid];

            float h1[H];
            #pragma unroll
            for (int k = 0; k < H; k++) {
                h1[k] = fmaxf(
                    fmaf(px, sW1[k],
                         fmaf(py, sW1[H + k],
                              fmaf(pz, sW1[2 * H + k], sb1[k]))), 0.0f);
            }

            float sig = sbias4[0], cr = sbias4[1], cg = sbias4[2], cb = sbias4[3];

            #pragma unroll 1
            for (int j0 = 0; j0 < H; j0 += 32) {
                unsigned long long acc[16];
                const ulonglong2* bv = (const ulonglong2*)(&sb2[j0]);
                #pragma unroll
                for (int p = 0; p < 8; p++) {
                    ulonglong2 t = bv[p];
                    acc[2 * p] = t.x;
                    acc[2 * p + 1] = t.y;
                }
                #pragma unroll
                for (int k = 0; k < H; k++) {
                    const unsigned long long hp = pack2(h1[k]);
                    const ulonglong2* wv = (const ulonglong2*)(&sW2[k * H + j0]);
                    #pragma unroll
                    for (int p = 0; p < 8; p++) {
                        ulonglong2 w = wv[p];
                        acc[2 * p]     = fma2(hp, w.x, acc[2 * p]);
                        acc[2 * p + 1] = fma2(hp, w.y, acc[2 * p + 1]);
                    }
                }
                #pragma unroll
                for (int p = 0; p < 16; p++) {
                    float lo, hi;
                    unpack2(acc[p], lo, hi);
                    lo = fmaxf(lo, 0.0f);
                    hi = fmaxf(hi, 0.0f);
                    const int j = j0 + 2 * p;
                    sig = fmaf(lo, sWsig[j], sig);
                    sig = fmaf(hi, sWsig[j + 1], sig);
                    cr = fmaf(lo, sWrgb[3 * j + 0], cr);
                    cr = fmaf(hi, sWrgb[3 * j + 3], cr);
                    cg = fmaf(lo, sWrgb[3 * j + 1], cg);
                    cg = fmaf(hi, sWrgb[3 * j + 4], cg);
                    cb = fmaf(lo, sWrgb[3 * j + 2], cb);
                    cb = fmaf(hi, sWrgb[3 * j + 5], cb);
                }
            }

            const float tau = fmaxf(sig, 0.0f) * step;
            const float alpha = 1.0f - expf(-tau);
            const float r = 1.0f / (1.0f + expf(-cr));
            const float g = 1.0f / (1.0f + expf(-cg));
            const float b = 1.0f / (1.0f + expf(-cb));

            const int o = s_orig[tid];
            s_alpha[o] = alpha;
            s_r[o] = r; s_g[o] = g; s_b[o] = b;
        }
        __syncthreads();

        // ---- phase C: warp-scan alpha composite (warp 0) ----
        if (tid < 32) {
            const int lane = tid;
            float ta[4];
            float pl = 1.0f;
            #pragma unroll
            for (int q = 0; q < 4; q++) {
                const float a = s_alpha[lane * 4 + q];
                ta[q] = 1.0f - a + 1e-10f;
                pl *= ta[q];
            }
            // inclusive product scan across lanes
            float inc = pl;
            #pragma unroll
            for (int off = 1; off < 32; off <<= 1) {
                const float v = __shfl_up_sync(0xffffffffu, inc, off);
                if (lane >= off) inc *= v;
            }
            const float total = __shfl_sync(0xffffffffu, inc, 31);
            float pre = __shfl_up_sync(0xffffffffu, inc, 1);
            if (lane == 0) pre = 1.0f;

            float T = pre, acr = 0.0f, acg = 0.0f, acb = 0.0f;
            #pragma unroll
            for (int q = 0; q < 4; q++) {
                const int i = lane * 4 + q;
                const float a = s_alpha[i];
                const float w = a * T;
                acr = fmaf(w, s_r[i], acr);
                acg = fmaf(w, s_g[i], acg);
                acb = fmaf(w, s_b[i], acb);
                T *= ta[q];
            }
            #pragma unroll
            for (int off = 16; off >= 1; off >>= 1) {
                acr += __shfl_xor_sync(0xffffffffu, acr, off);
                acg += __shfl_xor_sync(0xffffffffu, acg, off);
                acb += __shfl_xor_sync(0xffffffffu, acb, off);
            }
            if (lane == 0) {
                out[ray * 3 + 0] = acr + total;   // white background: + no_hit
                out[ray * 3 + 1] = acg + total;
                out[ray * 3 + 2] = acb + total;
            }
        }
        __syncthreads();
    }
}

extern "C" void kernel_launch(void* const* d_in, const int* in_sizes, int n_in,
                              void* d_out, int out_size) {
    const float* rays_o  = (const float*)d_in[0];
    const float* rays_d  = (const float*)d_in[1];
    const float* near_   = (const float*)d_in[2];
    const float* far_    = (const float*)d_in[3];
    const float* jitter  = (const float*)d_in[4];
    const float* density = (const float*)d_in[5];
    const float* W1      = (const float*)d_in[6];
    const float* b1      = (const float*)d_in[7];
    const float* W2      = (const float*)d_in[8];
    const float* b2      = (const float*)d_in[9];
    const float* Wsig    = (const float*)d_in[10];
    const float* bsig    = (const float*)d_in[11];
    const float* Wrgb    = (const float*)d_in[12];
    const float* brgb    = (const float*)d_in[13];
    float* out = (float*)d_out;

    const int nrays = in_sizes[2];   // near has N elements

    // persistent blocks: 148 SMs x 3 CTAs (launch_bounds cap 170 regs)
    render_kernel<<<444, 128>>>(rays_o, rays_d, near_, far_, jitter, density,
                                W1, b1, W2, b2, Wsig, bsig, Wrgb, brgb,
                                out, nrays);
}

// round 2
// speedup vs baseline: 1.3824x; 1.3824x over previous
#include <cuda_runtime.h>

#define S 128
#define H 64
#define GRIDR 64
#define RPB 4                 // rays per block iteration
#define POOL (RPB * S)        // 512 candidate samples

// ---- packed f32x2 helpers (sm_100+ PTX; ptxas never auto-emits FFMA2) ----
__device__ __forceinline__ unsigned long long pack2(float v) {
    unsigned long long r;
    unsigned int u = __float_as_uint(v);
    asm("mov.b64 %0, {%1,%2};" : "=l"(r) : "r"(u), "r"(u));
    return r;
}
__device__ __forceinline__ void unpack2(unsigned long long v, float& lo, float& hi) {
    unsigned int a, b;
    asm("mov.b64 {%0,%1}, %2;" : "=r"(a), "=r"(b) : "l"(v));
    lo = __uint_as_float(a);
    hi = __uint_as_float(b);
}
__device__ __forceinline__ unsigned long long fma2(unsigned long long a,
                                                   unsigned long long b,
                                                   unsigned long long c) {
    unsigned long long d;
    asm("fma.rn.f32x2 %0, %1, %2, %3;" : "=l"(d) : "l"(a), "l"(b), "l"(c));
    return d;
}

__global__ void __launch_bounds__(128, 3) render_kernel(
    const float* __restrict__ rays_o, const float* __restrict__ rays_d,
    const float* __restrict__ near_, const float* __restrict__ far_,
    const float* __restrict__ jitter, const float* __restrict__ density,
    const float* __restrict__ W1, const float* __restrict__ b1,
    const float* __restrict__ W2, const float* __restrict__ b2,
    const float* __restrict__ Wsig, const float* __restrict__ bsig,
    const float* __restrict__ Wrgb, const float* __restrict__ brgb,
    float* __restrict__ out, int nrays)
{
    __shared__ __align__(16) float sW2[H * H];     // 16 KB
    __shared__ __align__(16) float sb2[H];
    __shared__ float sW1[3 * H];
    __shared__ float sb1[H];
    __shared__ float sWsig[H];
    __shared__ float sWrgb[H * 3];
    __shared__ float sbias4[4];                    // bsig, brgb[0..2]
    __shared__ float s_px[POOL], s_py[POOL], s_pz[POOL];
    __shared__ int   s_orig[POOL];
    __shared__ float s_alpha[POOL], s_r[POOL], s_g[POOL], s_b[POOL];
    __shared__ float s_step[RPB];
    __shared__ int   s_cnt;

    const int tid = threadIdx.x;

    // ---- load weights to shared once per block (persistent blocks) ----
    for (int i = tid; i < 3 * H; i += 128) sW1[i] = W1[i];
    for (int i = tid; i < H; i += 128) {
        sb1[i] = b1[i]; sb2[i] = b2[i]; sWsig[i] = Wsig[i];
    }
    for (int i = tid; i < H * H; i += 128) sW2[i] = W2[i];
    for (int i = tid; i < H * 3; i += 128) sWrgb[i] = Wrgb[i];
    if (tid == 0) {
        sbias4[0] = bsig[0]; sbias4[1] = brgb[0];
        sbias4[2] = brgb[1]; sbias4[3] = brgb[2];
    }
    __syncthreads();

    const int ngroups = (nrays + RPB - 1) / RPB;

    for (int grp = blockIdx.x; grp < ngroups; grp += gridDim.x) {
        const int ray0 = grp * RPB;

        if (tid == 0) s_cnt = 0;
        #pragma unroll
        for (int q = 0; q < RPB; q++) {
            const int i = q * S + tid;
            s_alpha[i] = 0.0f; s_r[i] = 0.0f; s_g[i] = 0.0f; s_b[i] = 0.0f;
        }
        __syncthreads();

        // ---- phase A: grid occupancy test + compaction (4 rays) ----
        #pragma unroll
        for (int q = 0; q < RPB; q++) {
            const int ray = ray0 + q;
            if (ray >= nrays) break;
            const float ox = rays_o[ray * 3 + 0], oy = rays_o[ray * 3 + 1], oz = rays_o[ray * 3 + 2];
            const float dx = rays_d[ray * 3 + 0], dy = rays_d[ray * 3 + 1], dz = rays_d[ray * 3 + 2];
            const float nr = near_[ray], fr = far_[ray];
            const float step = (fr - nr) * (1.0f / (float)S);
            if (tid == 0) s_step[q] = step;

            const float z = nr + (float)tid * step;
            const float px0 = ox + z * dx;
            const float py0 = oy + z * dy;
            const float pz0 = oz + z * dz;
            // AABB: min=(-1.25,-1.55,-1.25), extent = 2.5 in all dims
            const float fx = ((px0 + 1.25f) * 0.4f) * 64.0f;
            const float fy = ((py0 + 1.55f) * 0.4f) * 64.0f;
            const float fz = ((pz0 + 1.25f) * 0.4f) * 64.0f;
            const int ix = (int)floorf(fx);
            const int iy = (int)floorf(fy);
            const int iz = (int)floorf(fz);
            const bool inb = (ix >= 0) & (ix < GRIDR) & (iy >= 0) & (iy < GRIDR) &
                             (iz >= 0) & (iz < GRIDR);
            bool active = false;
            if (inb) active = __ldg(&density[(ix * GRIDR + iy) * GRIDR + iz]) > 0.5f;

            float zv = active ? z : 0.0f;
            zv += jitter[ray * S + tid] * step;

            if (active) {
                const int slot = atomicAdd(&s_cnt, 1);
                s_px[slot] = ox + zv * dx;
                s_py[slot] = oy + zv * dy;
                s_pz[slot] = oz + zv * dz;
                s_orig[slot] = q * S + tid;
            }
        }
        __syncthreads();

        // ---- phase B: MLP over the compacted pool, all threads active ----
        const int nact = s_cnt;
        for (int base = 0; base < nact; base += 128) {
            const int si = base + tid;
            if (si < nact) {
                const float px = s_px[si], py = s_py[si], pz = s_pz[si];

                float h1[H];
                #pragma unroll
                for (int k = 0; k < H; k++) {
                    h1[k] = fmaxf(
                        fmaf(px, sW1[k],
                             fmaf(py, sW1[H + k],
                                  fmaf(pz, sW1[2 * H + k], sb1[k]))), 0.0f);
                }

                float sig = sbias4[0], cr = sbias4[1], cg = sbias4[2], cb = sbias4[3];

                #pragma unroll 1
                for (int j0 = 0; j0 < H; j0 += 32) {
                    unsigned long long acc[16];
                    const ulonglong2* bv = (const ulonglong2*)(&sb2[j0]);
                    #pragma unroll
                    for (int p = 0; p < 8; p++) {
                        ulonglong2 t = bv[p];
                        acc[2 * p] = t.x;
                        acc[2 * p + 1] = t.y;
                    }
                    #pragma unroll
                    for (int k = 0; k < H; k++) {
                        const unsigned long long hp = pack2(h1[k]);
                        const ulonglong2* wv = (const ulonglong2*)(&sW2[k * H + j0]);
                        #pragma unroll
                        for (int p = 0; p < 8; p++) {
                            ulonglong2 w = wv[p];
                            acc[2 * p]     = fma2(hp, w.x, acc[2 * p]);
                            acc[2 * p + 1] = fma2(hp, w.y, acc[2 * p + 1]);
                        }
                    }
                    #pragma unroll
                    for (int p = 0; p < 16; p++) {
                        float lo, hi;
                        unpack2(acc[p], lo, hi);
                        lo = fmaxf(lo, 0.0f);
                        hi = fmaxf(hi, 0.0f);
                        const int j = j0 + 2 * p;
                        sig = fmaf(lo, sWsig[j], sig);
                        sig = fmaf(hi, sWsig[j + 1], sig);
                        cr = fmaf(lo, sWrgb[3 * j + 0], cr);
                        cr = fmaf(hi, sWrgb[3 * j + 3], cr);
                        cg = fmaf(lo, sWrgb[3 * j + 1], cg);
                        cg = fmaf(hi, sWrgb[3 * j + 4], cg);
                        cb = fmaf(lo, sWrgb[3 * j + 2], cb);
                        cb = fmaf(hi, sWrgb[3 * j + 5], cb);
                    }
                }

                const int o = s_orig[si];
                const float step = s_step[o >> 7];   // o / S
                const float tau = fmaxf(sig, 0.0f) * step;
                const float alpha = 1.0f - expf(-tau);
                const float r = 1.0f / (1.0f + expf(-cr));
                const float g = 1.0f / (1.0f + expf(-cg));
                const float b = 1.0f / (1.0f + expf(-cb));

                s_alpha[o] = alpha;
                s_r[o] = r; s_g[o] = g; s_b[o] = b;
            }
        }
        __syncthreads();

        // ---- phase C: warp-scan alpha composite, one warp per ray ----
        {
            const int w = tid >> 5;
            const int lane = tid & 31;
            const int ray = ray0 + w;
            if (ray < nrays) {
                const int rb = w * S;
                float ta[4];
                float pl = 1.0f;
                #pragma unroll
                for (int q = 0; q < 4; q++) {
                    const float a = s_alpha[rb + lane * 4 + q];
                    ta[q] = 1.0f - a + 1e-10f;
                    pl *= ta[q];
                }
                // inclusive product scan across lanes
                float inc = pl;
                #pragma unroll
                for (int off = 1; off < 32; off <<= 1) {
                    const float v = __shfl_up_sync(0xffffffffu, inc, off);
                    if (lane >= off) inc *= v;
                }
                const float total = __shfl_sync(0xffffffffu, inc, 31);
                float pre = __shfl_up_sync(0xffffffffu, inc, 1);
                if (lane == 0) pre = 1.0f;

                float T = pre, acr = 0.0f, acg = 0.0f, acb = 0.0f;
                #pragma unroll
                for (int q = 0; q < 4; q++) {
                    const int i = rb + lane * 4 + q;
                    const float a = s_alpha[i];
                    const float wgt = a * T;
                    acr = fmaf(wgt, s_r[i], acr);
                    acg = fmaf(wgt, s_g[i], acg);
                    acb = fmaf(wgt, s_b[i], acb);
                    T *= ta[q];
                }
                #pragma unroll
                for (int off = 16; off >= 1; off >>= 1) {
                    acr += __shfl_xor_sync(0xffffffffu, acr, off);
                    acg += __shfl_xor_sync(0xffffffffu, acg, off);
                    acb += __shfl_xor_sync(0xffffffffu, acb, off);
                }
                if (lane == 0) {
                    out[ray * 3 + 0] = acr + total;   // white background: + no_hit
                    out[ray * 3 + 1] = acg + total;
                    out[ray * 3 + 2] = acb + total;
                }
            }
        }
        __syncthreads();
    }
}

extern "C" void kernel_launch(void* const* d_in, const int* in_sizes, int n_in,
                              void* d_out, int out_size) {
    const float* rays_o  = (const float*)d_in[0];
    const float* rays_d  = (const float*)d_in[1];
    const float* near_   = (const float*)d_in[2];
    const float* far_    = (const float*)d_in[3];
    const float* jitter  = (const float*)d_in[4];
    const float* density = (const float*)d_in[5];
    const float* W1      = (const float*)d_in[6];
    const float* b1      = (const float*)d_in[7];
    const float* W2      = (const float*)d_in[8];
    const float* b2      = (const float*)d_in[9];
    const float* Wsig    = (const float*)d_in[10];
    const float* bsig    = (const float*)d_in[11];
    const float* Wrgb    = (const float*)d_in[12];
    const float* brgb    = (const float*)d_in[13];
    float* out = (float*)d_out;

    const int nrays = in_sizes[2];   // near has N elements

    // persistent blocks: 148 SMs x 3 CTAs
    render_kernel<<<444, 128>>>(rays_o, rays_d, near_, far_, jitter, density,
                                W1, b1, W2, b2, Wsig, bsig, Wrgb, brgb,
                                out, nrays);
}